// round 14
// baseline (speedup 1.0000x reference)
#include <cuda_runtime.h>
#include <cstdint>

// Problem constants
#define Cc 192
#define SHIFTc 4

// ---- gmem scratch (static __device__) ----
__device__ float g_qkv[(size_t)4096 * 3 * 64 * 192];  // [win][p][t][c]
__device__ float g_o[(size_t)4096 * 64 * 192];        // [win][t][c]

__device__ __forceinline__ float to_tf32(float f) {
    uint32_t u;
    asm("cvt.rna.tf32.f32 %0, %1;" : "=r"(u) : "f"(f));
    return __uint_as_float(u);
}

__device__ __forceinline__ void mma8(float* c, const uint32_t* a, const uint32_t* b) {
    asm volatile(
        "mma.sync.aligned.m16n8k8.row.col.f32.tf32.tf32.f32 "
        "{%0,%1,%2,%3}, {%4,%5,%6,%7}, {%8,%9}, {%0,%1,%2,%3};"
        : "+f"(c[0]), "+f"(c[1]), "+f"(c[2]), "+f"(c[3])
        : "r"(a[0]), "r"(a[1]), "r"(a[2]), "r"(a[3]),
          "r"(b[0]), "r"(b[1]));
}

// =====================================================================
// Kernel A: QKV GEMM, 2 windows/CTA (M=128), 512 threads (16 warps),
// warp tile m32 x n48 (mt=2, nt=6), double-buffered weight chunk
// (ONE __syncthreads per chunk), LDG prefetch issued before MMA block.
// smem: A [128][196] = 100352 B ; Wt 2x[32][200] = 51200 B
// =====================================================================
#define LDA 196
#define LDB 200
#define QW_OFF 25088                 // floats (128*196)
#define QW_STRIDE 6400               // floats per W buffer
#define Q_SMEM_BYTES ((25088 + 12800) * 4)   // 151552

__global__ void __launch_bounds__(512, 1)
k_qkv(const float* __restrict__ x,
      const float* __restrict__ qkv_w,
      const float* __restrict__ qkv_b)
{
    extern __shared__ float smem[];
    float* Xs   = smem;              // [128][196]
    float* Wbuf = smem + QW_OFF;     // 2 x [32][200]

    const int tid  = threadIdx.x;
    const int warp = tid >> 5, lane = tid & 31;
    const int grp  = lane >> 2, tig = lane & 3;
    const int warp_m = warp >> 2;   // 0..3 (32 rows each)
    const int warp_n = warp & 3;    // 0..3 (48 cols each)
    const int bid = blockIdx.x;

    // ---- gather 2 windows with roll -> Xs[r][c] tf32 ----
    #pragma unroll 1
    for (int widx = 0; widx < 2; ++widx) {
        const int win = bid * 2 + widx;
        const int b = win >> 10, wy = (win >> 5) & 31, wx = win & 31;
        const int baseH = wy * 8 + SHIFTc, baseW = wx * 8 + SHIFTc;
        const float* xb = x + (size_t)b * Cc * 65536;
        #pragma unroll
        for (int i = 0; i < 24; ++i) {
            int idx = tid + i * 512;
            int c = idx >> 6, t = idx & 63;
            int ih = (baseH + (t >> 3)) & 255;
            int iw = (baseW + (t & 7)) & 255;
            Xs[(widx * 64 + t) * LDA + c] = to_tf32(xb[c * 65536 + ih * 256 + iw]);
        }
    }

    // ---- prefetch + stage weight chunk 0 into buffer 0 ----
    const int st_row = tid / 48;          // rows used below per j-slice
    float4 wreg[3];
    #pragma unroll
    for (int j = 0; j < 3; ++j) {
        int v4 = tid + j * 512;
        int row = v4 / 48, c4 = (v4 % 48) * 4;
        wreg[j] = *(const float4*)(qkv_w + (size_t)row * 576 + c4);
    }
    #pragma unroll
    for (int j = 0; j < 3; ++j) {
        int v4 = tid + j * 512;
        int row = v4 / 48, c4 = (v4 % 48) * 4;
        float4 w = wreg[j];
        w.x = to_tf32(w.x); w.y = to_tf32(w.y);
        w.z = to_tf32(w.z); w.w = to_tf32(w.w);
        *(float4*)(Wbuf + row * LDB + c4) = w;
    }
    __syncthreads();

    float acc[2][6][4];
    #pragma unroll
    for (int mt = 0; mt < 2; ++mt)
        #pragma unroll
        for (int nt = 0; nt < 6; ++nt)
            #pragma unroll
            for (int i = 0; i < 4; ++i) acc[mt][nt][i] = 0.0f;

    // flat loop over 18 chunks (pass p = cc/6, kc = cc%6)
    #pragma unroll 1
    for (int cc = 0; cc < 18; ++cc) {
        const int kc = cc % 6;
        const int p  = cc / 6;
        const float* Wt = Wbuf + (cc & 1) * QW_STRIDE;

        // prefetch next chunk from gmem (latency hidden by MMA block below)
        if (cc < 17) {
            const int cn = cc + 1, kcn = cn % 6, pn = cn / 6;
            #pragma unroll
            for (int j = 0; j < 3; ++j) {
                int v4 = tid + j * 512;
                int row = v4 / 48, c4 = (v4 % 48) * 4;
                wreg[j] = *(const float4*)(qkv_w + (size_t)(kcn * 32 + row) * 576 + pn * 192 + c4);
            }
        }

        // MMA block on current buffer
        #pragma unroll
        for (int ks = 0; ks < 4; ++ks) {
            const int kb = kc * 32 + ks * 8;
            uint32_t a[2][4];
            #pragma unroll
            for (int mt = 0; mt < 2; ++mt) {
                const float* ap = Xs + (warp_m * 32 + mt * 16 + grp) * LDA + kb + tig;
                a[mt][0] = __float_as_uint(ap[0]);
                a[mt][1] = __float_as_uint(ap[8 * LDA]);
                a[mt][2] = __float_as_uint(ap[4]);
                a[mt][3] = __float_as_uint(ap[8 * LDA + 4]);
            }
            uint32_t bb[6][2];
            #pragma unroll
            for (int nt = 0; nt < 6; ++nt) {
                const float* bp = Wt + (ks * 8 + tig) * LDB + warp_n * 48 + nt * 8 + grp;
                bb[nt][0] = __float_as_uint(bp[0]);
                bb[nt][1] = __float_as_uint(bp[4 * LDB]);
            }
            #pragma unroll
            for (int mt = 0; mt < 2; ++mt)
                #pragma unroll
                for (int nt = 0; nt < 6; ++nt)
                    mma8(acc[mt][nt], a[mt], bb[nt]);
        }

        // stage next chunk into other buffer (no reader conflict: prev-chunk
        // readers of that buffer were fenced by last iteration's barrier)
        if (cc < 17) {
            float* Wn = Wbuf + ((cc + 1) & 1) * QW_STRIDE;
            #pragma unroll
            for (int j = 0; j < 3; ++j) {
                int v4 = tid + j * 512;
                int row = v4 / 48, c4 = (v4 % 48) * 4;
                float4 w = wreg[j];
                w.x = to_tf32(w.x); w.y = to_tf32(w.y);
                w.z = to_tf32(w.z); w.w = to_tf32(w.w);
                *(float4*)(Wn + row * LDB + c4) = w;
            }
        }

        // end of pass: bias + store + reset acc (registers + gmem only)
        if (kc == 5) {
            #pragma unroll
            for (int nt = 0; nt < 6; ++nt) {
                int col = warp_n * 48 + nt * 8 + 2 * tig;
                float b0 = __ldg(qkv_b + p * 192 + col);
                float b1 = __ldg(qkv_b + p * 192 + col + 1);
                #pragma unroll
                for (int mt = 0; mt < 2; ++mt) {
                    int r = warp_m * 32 + mt * 16 + grp;
                    int win = bid * 2 + (r >> 6), t = r & 63;
                    float* dst = g_qkv + (size_t)win * 36864 + p * 12288 + t * 192 + col;
                    *(float2*)dst =
                        make_float2(to_tf32(acc[mt][nt][0] + b0), to_tf32(acc[mt][nt][1] + b1));
                    *(float2*)(dst + 8 * 192) =
                        make_float2(to_tf32(acc[mt][nt][2] + b0), to_tf32(acc[mt][nt][3] + b1));
                    acc[mt][nt][0] = 0.0f; acc[mt][nt][1] = 0.0f;
                    acc[mt][nt][2] = 0.0f; acc[mt][nt][3] = 0.0f;
                }
            }
        }
        __syncthreads();   // single barrier per chunk
    }
}

// =====================================================================
// Kernel B: attention per (window, head) — unchanged from round 9.
// =====================================================================
#define LDH  36
#define LDVH 40
#define LDS2 68
#define B_SMEM_BYTES ((2304 + 2304 + 2560 + 4352) * 4)

__global__ void __launch_bounds__(128, 4)
k_attn()
{
    extern __shared__ float smemf[];
    float* Qh = smemf;
    float* Kh = smemf + 2304;
    float* Vh = smemf + 4608;
    float* S  = smemf + 7168;

    const int tid  = threadIdx.x;
    const int warp = tid >> 5, lane = tid & 31;
    const int grp  = lane >> 2, tig = lane & 3;
    const int win = blockIdx.x, h = blockIdx.y;

    {
        const float* src = g_qkv + (size_t)win * 36864 + h * 32;
        int r = tid >> 3, f4 = (tid & 7) * 4;
        #pragma unroll
        for (int it = 0; it < 4; ++it) {
            int t = r + it * 16;
            float4 q = *(const float4*)(src + t * 192 + f4);
            float4 k = *(const float4*)(src + 12288 + t * 192 + f4);
            float4 v = *(const float4*)(src + 24576 + t * 192 + f4);
            *(float4*)(Qh + t * LDH + f4)  = q;
            *(float4*)(Kh + t * LDH + f4)  = k;
            *(float4*)(Vh + t * LDVH + f4) = v;
        }
    }
    __syncthreads();

    float sacc[8][4];
    #pragma unroll
    for (int nt = 0; nt < 8; ++nt)
        #pragma unroll
        for (int i = 0; i < 4; ++i) sacc[nt][i] = 0.0f;

    #pragma unroll
    for (int ks = 0; ks < 4; ++ks) {
        int kb = ks * 8;
        uint32_t a[4];
        const float* ap = Qh + (warp * 16 + grp) * LDH + kb + tig;
        a[0] = __float_as_uint(ap[0]);
        a[1] = __float_as_uint(ap[8 * LDH]);
        a[2] = __float_as_uint(ap[4]);
        a[3] = __float_as_uint(ap[8 * LDH + 4]);
        #pragma unroll
        for (int nt = 0; nt < 8; ++nt) {
            uint32_t bb[2];
            const float* bp = Kh + (nt * 8 + grp) * LDH + kb + tig;
            bb[0] = __float_as_uint(bp[0]);
            bb[1] = __float_as_uint(bp[4]);
            mma8(sacc[nt], a, bb);
        }
    }
    const float scale = 0.17677669529663687f;
    #pragma unroll
    for (int nt = 0; nt < 8; ++nt) {
        int col = nt * 8 + 2 * tig;
        int r0 = warp * 16 + grp;
        *(float2*)(S + r0 * LDS2 + col) =
            make_float2(sacc[nt][0] * scale, sacc[nt][1] * scale);
        *(float2*)(S + (r0 + 8) * LDS2 + col) =
            make_float2(sacc[nt][2] * scale, sacc[nt][3] * scale);
    }
    __syncwarp();

    #pragma unroll 1
    for (int rr = 0; rr < 16; ++rr) {
        int row = warp * 16 + rr;
        float v0 = S[row * LDS2 + lane];
        float v1 = S[row * LDS2 + 32 + lane];
        float m = fmaxf(v0, v1);
        #pragma unroll
        for (int off = 16; off > 0; off >>= 1)
            m = fmaxf(m, __shfl_xor_sync(0xFFFFFFFFu, m, off));
        float e0 = __expf(v0 - m);
        float e1 = __expf(v1 - m);
        float s = e0 + e1;
        #pragma unroll
        for (int off = 16; off > 0; off >>= 1)
            s += __shfl_xor_sync(0xFFFFFFFFu, s, off);
        float inv = __frcp_rn(s);
        S[row * LDS2 + lane]      = to_tf32(e0 * inv);
        S[row * LDS2 + 32 + lane] = to_tf32(e1 * inv);
    }
    __syncwarp();

    float oacc[4][4];
    #pragma unroll
    for (int nt = 0; nt < 4; ++nt)
        #pragma unroll
        for (int i = 0; i < 4; ++i) oacc[nt][i] = 0.0f;

    #pragma unroll
    for (int ks = 0; ks < 8; ++ks) {
        uint32_t a[4];
        const float* ap = S + (warp * 16 + grp) * LDS2 + ks * 8 + tig;
        a[0] = __float_as_uint(ap[0]);
        a[1] = __float_as_uint(ap[8 * LDS2]);
        a[2] = __float_as_uint(ap[4]);
        a[3] = __float_as_uint(ap[8 * LDS2 + 4]);
        #pragma unroll
        for (int nt = 0; nt < 4; ++nt) {
            uint32_t bb[2];
            const float* bp = Vh + (ks * 8 + tig) * LDVH + nt * 8 + grp;
            bb[0] = __float_as_uint(bp[0]);
            bb[1] = __float_as_uint(bp[4 * LDVH]);
            mma8(oacc[nt], a, bb);
        }
    }
    float* dst = g_o + (size_t)win * 12288 + h * 32;
    #pragma unroll
    for (int nt = 0; nt < 4; ++nt) {
        int col = nt * 8 + 2 * tig;
        int r0 = warp * 16 + grp;
        *(float2*)(dst + r0 * 192 + col) =
            make_float2(to_tf32(oacc[nt][0]), to_tf32(oacc[nt][1]));
        *(float2*)(dst + (r0 + 8) * 192 + col) =
            make_float2(to_tf32(oacc[nt][2]), to_tf32(oacc[nt][3]));
    }
}

// =====================================================================
// Kernel C: proj GEMM, 2 windows/CTA, 512 threads, m32 x n48 warp tile,
// double-buffered W (one sync per chunk), roll-scatter from registers.
// =====================================================================
__global__ void __launch_bounds__(512, 1)
k_proj(const float* __restrict__ proj_w,
       const float* __restrict__ proj_b,
       float* __restrict__ out)
{
    extern __shared__ float smem[];
    float* Os   = smem;              // [128][196]
    float* Wbuf = smem + QW_OFF;     // 2 x [32][200]

    const int tid  = threadIdx.x;
    const int warp = tid >> 5, lane = tid & 31;
    const int grp  = lane >> 2, tig = lane & 3;
    const int warp_m = warp >> 2;
    const int warp_n = warp & 3;
    const int bid = blockIdx.x;

    // stage A: O tiles of 2 windows (already tf32), float4 coalesced
    #pragma unroll 1
    for (int widx = 0; widx < 2; ++widx) {
        const float* src = g_o + (size_t)(bid * 2 + widx) * 12288;
        #pragma unroll
        for (int i = 0; i < 6; ++i) {
            int idx = tid + i * 512;          // 3072 float4 per window
            int t = idx / 48, q4 = (idx % 48) * 4;
            *(float4*)(Os + (widx * 64 + t) * LDA + q4) = *(const float4*)(src + t * 192 + q4);
        }
    }

    // prefetch + stage W chunk 0
    float4 wreg[3];
    #pragma unroll
    for (int j = 0; j < 3; ++j)
        wreg[j] = ((const float4*)proj_w)[tid + j * 512];
    #pragma unroll
    for (int j = 0; j < 3; ++j) {
        int v4 = tid + j * 512;
        int row = v4 / 48, c4 = (v4 % 48) * 4;
        float4 w = wreg[j];
        w.x = to_tf32(w.x); w.y = to_tf32(w.y);
        w.z = to_tf32(w.z); w.w = to_tf32(w.w);
        *(float4*)(Wbuf + row * LDB + c4) = w;
    }
    __syncthreads();

    float acc[2][6][4];
    #pragma unroll
    for (int mt = 0; mt < 2; ++mt)
        #pragma unroll
        for (int nt = 0; nt < 6; ++nt)
            #pragma unroll
            for (int i = 0; i < 4; ++i) acc[mt][nt][i] = 0.0f;

    #pragma unroll 1
    for (int kc = 0; kc < 6; ++kc) {
        const float* Wt = Wbuf + (kc & 1) * QW_STRIDE;

        if (kc < 5) {
            #pragma unroll
            for (int j = 0; j < 3; ++j)
                wreg[j] = ((const float4*)(proj_w + (kc + 1) * 6144))[tid + j * 512];
        }

        #pragma unroll
        for (int ks = 0; ks < 4; ++ks) {
            const int kb = kc * 32 + ks * 8;
            uint32_t a[2][4];
            #pragma unroll
            for (int mt = 0; mt < 2; ++mt) {
                const float* ap = Os + (warp_m * 32 + mt * 16 + grp) * LDA + kb + tig;
                a[mt][0] = __float_as_uint(ap[0]);
                a[mt][1] = __float_as_uint(ap[8 * LDA]);
                a[mt][2] = __float_as_uint(ap[4]);
                a[mt][3] = __float_as_uint(ap[8 * LDA + 4]);
            }
            uint32_t bb[6][2];
            #pragma unroll
            for (int nt = 0; nt < 6; ++nt) {
                const float* bp = Wt + (ks * 8 + tig) * LDB + warp_n * 48 + nt * 8 + grp;
                bb[nt][0] = __float_as_uint(bp[0]);
                bb[nt][1] = __float_as_uint(bp[4 * LDB]);
            }
            #pragma unroll
            for (int mt = 0; mt < 2; ++mt)
                #pragma unroll
                for (int nt = 0; nt < 6; ++nt)
                    mma8(acc[mt][nt], a[mt], bb[nt]);
        }

        if (kc < 5) {
            float* Wn = Wbuf + ((kc + 1) & 1) * QW_STRIDE;
            #pragma unroll
            for (int j = 0; j < 3; ++j) {
                int v4 = tid + j * 512;
                int row = v4 / 48, c4 = (v4 % 48) * 4;
                float4 w = wreg[j];
                w.x = to_tf32(w.x); w.y = to_tf32(w.y);
                w.z = to_tf32(w.z); w.w = to_tf32(w.w);
                *(float4*)(Wn + row * LDB + c4) = w;
            }
            __syncthreads();
        }
    }

    // epilogue: bias + roll-scatter straight from registers (NCHW)
    #pragma unroll
    for (int nt = 0; nt < 6; ++nt) {
        int col = warp_n * 48 + nt * 8 + 2 * tig;
        float b0 = __ldg(proj_b + col);
        float b1 = __ldg(proj_b + col + 1);
        #pragma unroll
        for (int mt = 0; mt < 2; ++mt) {
            int r = warp_m * 32 + mt * 16 + grp;
            int win = bid * 2 + (r >> 6);
            int b = win >> 10, wy = (win >> 5) & 31, wx = win & 31;
            int t0 = r & 63;
            int oh0 = ((wy * 8 + SHIFTc) + (t0 >> 3)) & 255;
            int oh1 = ((wy * 8 + SHIFTc) + ((t0 + 8) >> 3)) & 255;
            int ow  = ((wx * 8 + SHIFTc) + (t0 & 7)) & 255;
            float* o0 = out + (size_t)b * Cc * 65536 + (size_t)col * 65536;
            float* o1 = o0 + 65536;
            o0[oh0 * 256 + ow] = acc[mt][nt][0] + b0;
            o1[oh0 * 256 + ow] = acc[mt][nt][1] + b1;
            o0[oh1 * 256 + ow] = acc[mt][nt][2] + b0;
            o1[oh1 * 256 + ow] = acc[mt][nt][3] + b1;
        }
    }
}

extern "C" void kernel_launch(void* const* d_in, const int* in_sizes, int n_in,
                              void* d_out, int out_size)
{
    const float* x      = (const float*)d_in[0];
    const float* qkv_w  = (const float*)d_in[1];
    const float* qkv_b  = (const float*)d_in[2];
    const float* proj_w = (const float*)d_in[3];
    const float* proj_b = (const float*)d_in[4];
    float* out = (float*)d_out;

    cudaFuncSetAttribute(k_qkv,  cudaFuncAttributeMaxDynamicSharedMemorySize, Q_SMEM_BYTES);
    cudaFuncSetAttribute(k_attn, cudaFuncAttributeMaxDynamicSharedMemorySize, B_SMEM_BYTES);
    cudaFuncSetAttribute(k_proj, cudaFuncAttributeMaxDynamicSharedMemorySize, Q_SMEM_BYTES);

    k_qkv<<<2048, 512, Q_SMEM_BYTES>>>(x, qkv_w, qkv_b);
    dim3 gb(4096, 6);
    k_attn<<<gb, 128, B_SMEM_BYTES>>>();
    k_proj<<<2048, 512, Q_SMEM_BYTES>>>(proj_w, proj_b, out);
}

// round 15
// speedup vs baseline: 1.0183x; 1.0183x over previous
#include <cuda_runtime.h>
#include <cstdint>

// Problem constants
#define Cc 192
#define SHIFTc 4

// ---- gmem scratch (static __device__) ----
__device__ float g_qkv[(size_t)4096 * 3 * 64 * 192];  // [win][p][t][c]
__device__ float g_o[(size_t)4096 * 64 * 192];        // [win][t][c]

__device__ __forceinline__ float to_tf32(float f) {
    uint32_t u;
    asm("cvt.rna.tf32.f32 %0, %1;" : "=r"(u) : "f"(f));
    return __uint_as_float(u);
}

__device__ __forceinline__ void mma8(float* c, const uint32_t* a, const uint32_t* b) {
    asm volatile(
        "mma.sync.aligned.m16n8k8.row.col.f32.tf32.tf32.f32 "
        "{%0,%1,%2,%3}, {%4,%5,%6,%7}, {%8,%9}, {%0,%1,%2,%3};"
        : "+f"(c[0]), "+f"(c[1]), "+f"(c[2]), "+f"(c[3])
        : "r"(a[0]), "r"(a[1]), "r"(a[2]), "r"(a[3]),
          "r"(b[0]), "r"(b[1]));
}

// =====================================================================
// Kernel A: QKV GEMM. 1 window/CTA (M=64), 256 threads (8 warps),
// warp tile m64 x n24 (mt=4, nt=3), 16-row W chunk, single-buffered.
// smem: Xs[64][196]=50176B + Wc[16][200]=12800B = 62976B -> 3 CTAs/SM.
// =====================================================================
#define LDA 196
#define LDB 200
#define G_OFF_W 12544                // floats (64*196)
#define G_SMEM_BYTES ((12544 + 3200) * 4)   // 62976

__global__ void __launch_bounds__(256, 3)
k_qkv(const float* __restrict__ x,
      const float* __restrict__ qkv_w,
      const float* __restrict__ qkv_b)
{
    extern __shared__ float smem[];
    float* Xs = smem;              // [64][196]
    float* Wc = smem + G_OFF_W;    // [16][200]

    const int tid  = threadIdx.x;
    const int warp = tid >> 5, lane = tid & 31;
    const int grp  = lane >> 2, tig = lane & 3;
    const int warp_n = warp;       // 0..7, 24 cols each (covers 192)
    const int win = blockIdx.x;
    const int b = win >> 10, wy = (win >> 5) & 31, wx = win & 31;
    const int baseH = wy * 8 + SHIFTc, baseW = wx * 8 + SHIFTc;

    // ---- gather window with roll -> Xs[t][c] tf32 ----
    {
        const float* xb = x + (size_t)b * Cc * 65536;
        #pragma unroll
        for (int i = 0; i < 48; ++i) {
            int idx = tid + i * 256;
            int c = idx >> 6, t = idx & 63;
            int ih = (baseH + (t >> 3)) & 255;
            int iw = (baseW + (t & 7)) & 255;
            Xs[t * LDA + c] = to_tf32(xb[c * 65536 + ih * 256 + iw]);
        }
    }

    float acc[4][3][4];
    #pragma unroll
    for (int mt = 0; mt < 4; ++mt)
        #pragma unroll
        for (int nt = 0; nt < 3; ++nt)
            #pragma unroll
            for (int i = 0; i < 4; ++i) acc[mt][nt][i] = 0.0f;

    // 36 chunks: pass p = cc/12, kc = cc%12 (16 k-rows each)
    #pragma unroll 1
    for (int cc = 0; cc < 36; ++cc) {
        const int kc = cc % 12;
        const int p  = cc / 12;

        __syncthreads();   // previous chunk consumers done (A ready at cc=0)
        // stage W rows [kc*16, +16), cols [p*192, +192): 768 float4, 3/thread
        #pragma unroll
        for (int j = 0; j < 3; ++j) {
            int v4 = tid + j * 256;
            int row = v4 / 48, c4 = (v4 % 48) * 4;
            float4 w = *(const float4*)(qkv_w + (size_t)(kc * 16 + row) * 576 + p * 192 + c4);
            w.x = to_tf32(w.x); w.y = to_tf32(w.y);
            w.z = to_tf32(w.z); w.w = to_tf32(w.w);
            *(float4*)(Wc + row * LDB + c4) = w;
        }
        __syncthreads();

        #pragma unroll
        for (int ks = 0; ks < 2; ++ks) {
            const int kb = kc * 16 + ks * 8;
            uint32_t a[4][4];
            #pragma unroll
            for (int mt = 0; mt < 4; ++mt) {
                const float* ap = Xs + (mt * 16 + grp) * LDA + kb + tig;
                a[mt][0] = __float_as_uint(ap[0]);
                a[mt][1] = __float_as_uint(ap[8 * LDA]);
                a[mt][2] = __float_as_uint(ap[4]);
                a[mt][3] = __float_as_uint(ap[8 * LDA + 4]);
            }
            uint32_t bb[3][2];
            #pragma unroll
            for (int nt = 0; nt < 3; ++nt) {
                const float* bp = Wc + (ks * 8 + tig) * LDB + warp_n * 24 + nt * 8 + grp;
                bb[nt][0] = __float_as_uint(bp[0]);
                bb[nt][1] = __float_as_uint(bp[4 * LDB]);
            }
            #pragma unroll
            for (int mt = 0; mt < 4; ++mt)
                #pragma unroll
                for (int nt = 0; nt < 3; ++nt)
                    mma8(acc[mt][nt], a[mt], bb[nt]);
        }

        // end of pass: bias + store + reset acc
        if (kc == 11) {
            #pragma unroll
            for (int nt = 0; nt < 3; ++nt) {
                int col = warp_n * 24 + nt * 8 + 2 * tig;
                float b0 = __ldg(qkv_b + p * 192 + col);
                float b1 = __ldg(qkv_b + p * 192 + col + 1);
                #pragma unroll
                for (int mt = 0; mt < 4; ++mt) {
                    int r = mt * 16 + grp;
                    float* dst = g_qkv + (size_t)win * 36864 + p * 12288 + r * 192 + col;
                    *(float2*)dst =
                        make_float2(to_tf32(acc[mt][nt][0] + b0), to_tf32(acc[mt][nt][1] + b1));
                    *(float2*)(dst + 8 * 192) =
                        make_float2(to_tf32(acc[mt][nt][2] + b0), to_tf32(acc[mt][nt][3] + b1));
                    acc[mt][nt][0] = 0.0f; acc[mt][nt][1] = 0.0f;
                    acc[mt][nt][2] = 0.0f; acc[mt][nt][3] = 0.0f;
                }
            }
        }
    }
}

// =====================================================================
// Kernel B: attention per (window, head). 128 threads.
// Q fragments in REGISTERS direct from gmem (no Qh smem).
// smem: Kh[64][36] + Vh[64][40] + S[64][68] = 36864B -> 6 CTAs/SM.
// =====================================================================
#define LDH  36
#define LDVH 40
#define LDS2 68
#define B_SMEM_BYTES ((2304 + 2560 + 4352) * 4)   // 36864

__global__ void __launch_bounds__(128, 6)
k_attn()
{
    extern __shared__ float smemf[];
    float* Kh = smemf;
    float* Vh = smemf + 2304;
    float* S  = smemf + 4864;

    const int tid  = threadIdx.x;
    const int warp = tid >> 5, lane = tid & 31;
    const int grp  = lane >> 2, tig = lane & 3;
    const int win = blockIdx.x, h = blockIdx.y;

    // Q fragments direct from gmem (warp-private rows warp*16..+15)
    uint32_t qa[4][4];
    {
        const float* qsrc = g_qkv + (size_t)win * 36864 + h * 32
                          + (warp * 16 + grp) * 192 + tig;
        #pragma unroll
        for (int ks = 0; ks < 4; ++ks) {
            qa[ks][0] = __float_as_uint(qsrc[ks * 8]);
            qa[ks][1] = __float_as_uint(qsrc[8 * 192 + ks * 8]);
            qa[ks][2] = __float_as_uint(qsrc[ks * 8 + 4]);
            qa[ks][3] = __float_as_uint(qsrc[8 * 192 + ks * 8 + 4]);
        }
    }

    // stage K,V head slices into smem
    {
        const float* src = g_qkv + (size_t)win * 36864 + h * 32;
        int r = tid >> 3, f4 = (tid & 7) * 4;
        #pragma unroll
        for (int it = 0; it < 4; ++it) {
            int t = r + it * 16;
            float4 k = *(const float4*)(src + 12288 + t * 192 + f4);
            float4 v = *(const float4*)(src + 24576 + t * 192 + f4);
            *(float4*)(Kh + t * LDH + f4)  = k;
            *(float4*)(Vh + t * LDVH + f4) = v;
        }
    }
    __syncthreads();

    // S = scale * Q @ K^T : warp owns rows warp*16..+15, all 64 cols
    float sacc[8][4];
    #pragma unroll
    for (int nt = 0; nt < 8; ++nt)
        #pragma unroll
        for (int i = 0; i < 4; ++i) sacc[nt][i] = 0.0f;

    #pragma unroll
    for (int ks = 0; ks < 4; ++ks) {
        int kb = ks * 8;
        #pragma unroll
        for (int nt = 0; nt < 8; ++nt) {
            uint32_t bb[2];
            const float* bp = Kh + (nt * 8 + grp) * LDH + kb + tig;
            bb[0] = __float_as_uint(bp[0]);
            bb[1] = __float_as_uint(bp[4]);
            mma8(sacc[nt], qa[ks], bb);
        }
    }
    const float scale = 0.17677669529663687f;
    #pragma unroll
    for (int nt = 0; nt < 8; ++nt) {
        int col = nt * 8 + 2 * tig;
        int r0 = warp * 16 + grp;
        *(float2*)(S + r0 * LDS2 + col) =
            make_float2(sacc[nt][0] * scale, sacc[nt][1] * scale);
        *(float2*)(S + (r0 + 8) * LDS2 + col) =
            make_float2(sacc[nt][2] * scale, sacc[nt][3] * scale);
    }
    __syncwarp();

    // softmax: 16 rows per warp (its own rows)
    #pragma unroll 1
    for (int rr = 0; rr < 16; ++rr) {
        int row = warp * 16 + rr;
        float v0 = S[row * LDS2 + lane];
        float v1 = S[row * LDS2 + 32 + lane];
        float m = fmaxf(v0, v1);
        #pragma unroll
        for (int off = 16; off > 0; off >>= 1)
            m = fmaxf(m, __shfl_xor_sync(0xFFFFFFFFu, m, off));
        float e0 = __expf(v0 - m);
        float e1 = __expf(v1 - m);
        float s = e0 + e1;
        #pragma unroll
        for (int off = 16; off > 0; off >>= 1)
            s += __shfl_xor_sync(0xFFFFFFFFu, s, off);
        float inv = __frcp_rn(s);
        S[row * LDS2 + lane]      = to_tf32(e0 * inv);
        S[row * LDS2 + 32 + lane] = to_tf32(e1 * inv);
    }
    __syncwarp();

    // O = P @ V : m16 x n32 per warp, K=64
    float oacc[4][4];
    #pragma unroll
    for (int nt = 0; nt < 4; ++nt)
        #pragma unroll
        for (int i = 0; i < 4; ++i) oacc[nt][i] = 0.0f;

    #pragma unroll
    for (int ks = 0; ks < 8; ++ks) {
        uint32_t a[4];
        const float* ap = S + (warp * 16 + grp) * LDS2 + ks * 8 + tig;
        a[0] = __float_as_uint(ap[0]);
        a[1] = __float_as_uint(ap[8 * LDS2]);
        a[2] = __float_as_uint(ap[4]);
        a[3] = __float_as_uint(ap[8 * LDS2 + 4]);
        #pragma unroll
        for (int nt = 0; nt < 4; ++nt) {
            uint32_t bb[2];
            const float* bp = Vh + (ks * 8 + tig) * LDVH + nt * 8 + grp;
            bb[0] = __float_as_uint(bp[0]);
            bb[1] = __float_as_uint(bp[4 * LDVH]);
            mma8(oacc[nt], a, bb);
        }
    }
    float* dst = g_o + (size_t)win * 12288 + h * 32;
    #pragma unroll
    for (int nt = 0; nt < 4; ++nt) {
        int col = nt * 8 + 2 * tig;
        int r0 = warp * 16 + grp;
        *(float2*)(dst + r0 * 192 + col) =
            make_float2(to_tf32(oacc[nt][0]), to_tf32(oacc[nt][1]));
        *(float2*)(dst + (r0 + 8) * 192 + col) =
            make_float2(to_tf32(oacc[nt][2]), to_tf32(oacc[nt][3]));
    }
}

// =====================================================================
// Kernel C: proj GEMM. 1 window/CTA, 256 threads, warp tile m64 x n24,
// 16-row W chunks, roll-scatter from registers. smem 62976B -> 3 CTAs/SM.
// =====================================================================
__global__ void __launch_bounds__(256, 3)
k_proj(const float* __restrict__ proj_w,
       const float* __restrict__ proj_b,
       float* __restrict__ out)
{
    extern __shared__ float smem[];
    float* Os = smem;              // [64][196]
    float* Wc = smem + G_OFF_W;    // [16][200]

    const int tid  = threadIdx.x;
    const int warp = tid >> 5, lane = tid & 31;
    const int grp  = lane >> 2, tig = lane & 3;
    const int warp_n = warp;       // 0..7
    const int win = blockIdx.x;
    const int b = win >> 10, wy = (win >> 5) & 31, wx = win & 31;
    const int baseH = wy * 8 + SHIFTc, baseW = wx * 8 + SHIFTc;

    // stage O tile (already tf32), float4 coalesced
    {
        const float4* src = (const float4*)(g_o + (size_t)win * 12288);
        #pragma unroll
        for (int i = 0; i < 12; ++i) {
            int idx = tid + i * 256;           // 3072 float4
            int t = idx / 48, q4 = (idx % 48) * 4;
            *(float4*)(Os + t * LDA + q4) = src[idx];
        }
    }

    float acc[4][3][4];
    #pragma unroll
    for (int mt = 0; mt < 4; ++mt)
        #pragma unroll
        for (int nt = 0; nt < 3; ++nt)
            #pragma unroll
            for (int i = 0; i < 4; ++i) acc[mt][nt][i] = 0.0f;

    #pragma unroll 1
    for (int kc = 0; kc < 12; ++kc) {
        __syncthreads();
        #pragma unroll
        for (int j = 0; j < 3; ++j) {
            int v4 = tid + j * 256;
            int row = v4 / 48, c4 = (v4 % 48) * 4;
            float4 w = *(const float4*)(proj_w + (size_t)(kc * 16 + row) * 192 + c4);
            w.x = to_tf32(w.x); w.y = to_tf32(w.y);
            w.z = to_tf32(w.z); w.w = to_tf32(w.w);
            *(float4*)(Wc + row * LDB + c4) = w;
        }
        __syncthreads();

        #pragma unroll
        for (int ks = 0; ks < 2; ++ks) {
            const int kb = kc * 16 + ks * 8;
            uint32_t a[4][4];
            #pragma unroll
            for (int mt = 0; mt < 4; ++mt) {
                const float* ap = Os + (mt * 16 + grp) * LDA + kb + tig;
                a[mt][0] = __float_as_uint(ap[0]);
                a[mt][1] = __float_as_uint(ap[8 * LDA]);
                a[mt][2] = __float_as_uint(ap[4]);
                a[mt][3] = __float_as_uint(ap[8 * LDA + 4]);
            }
            uint32_t bb[3][2];
            #pragma unroll
            for (int nt = 0; nt < 3; ++nt) {
                const float* bp = Wc + (ks * 8 + tig) * LDB + warp_n * 24 + nt * 8 + grp;
                bb[nt][0] = __float_as_uint(bp[0]);
                bb[nt][1] = __float_as_uint(bp[4 * LDB]);
            }
            #pragma unroll
            for (int mt = 0; mt < 4; ++mt)
                #pragma unroll
                for (int nt = 0; nt < 3; ++nt)
                    mma8(acc[mt][nt], a[mt], bb[nt]);
        }
    }

    // epilogue: bias + roll-scatter straight from registers (NCHW)
    const int ow = (baseW + grp) & 255;
    #pragma unroll
    for (int nt = 0; nt < 3; ++nt) {
        int col = warp_n * 24 + nt * 8 + 2 * tig;
        float b0 = __ldg(proj_b + col);
        float b1 = __ldg(proj_b + col + 1);
        #pragma unroll
        for (int mt = 0; mt < 4; ++mt) {
            int t0 = mt * 16 + grp;
            int oh0 = (baseH + (t0 >> 3)) & 255;
            int oh1 = (baseH + ((t0 + 8) >> 3)) & 255;
            float* o0 = out + (size_t)b * Cc * 65536 + (size_t)col * 65536;
            float* o1 = o0 + 65536;
            o0[oh0 * 256 + ow] = acc[mt][nt][0] + b0;
            o1[oh0 * 256 + ow] = acc[mt][nt][1] + b1;
            o0[oh1 * 256 + ow] = acc[mt][nt][2] + b0;
            o1[oh1 * 256 + ow] = acc[mt][nt][3] + b1;
        }
    }
}

extern "C" void kernel_launch(void* const* d_in, const int* in_sizes, int n_in,
                              void* d_out, int out_size)
{
    const float* x      = (const float*)d_in[0];
    const float* qkv_w  = (const float*)d_in[1];
    const float* qkv_b  = (const float*)d_in[2];
    const float* proj_w = (const float*)d_in[3];
    const float* proj_b = (const float*)d_in[4];
    float* out = (float*)d_out;

    cudaFuncSetAttribute(k_qkv,  cudaFuncAttributeMaxDynamicSharedMemorySize, G_SMEM_BYTES);
    cudaFuncSetAttribute(k_attn, cudaFuncAttributeMaxDynamicSharedMemorySize, B_SMEM_BYTES);
    cudaFuncSetAttribute(k_proj, cudaFuncAttributeMaxDynamicSharedMemorySize, G_SMEM_BYTES);

    k_qkv<<<4096, 256, G_SMEM_BYTES>>>(x, qkv_w, qkv_b);
    dim3 gb(4096, 6);
    k_attn<<<gb, 128, B_SMEM_BYTES>>>();
    k_proj<<<4096, 256, G_SMEM_BYTES>>>(proj_w, proj_b, out);
}

// round 16
// speedup vs baseline: 1.6154x; 1.5864x over previous
#include <cuda_runtime.h>
#include <cuda_fp16.h>
#include <cstdint>

// Problem constants
#define Cc 192
#define SHIFTc 4

// ---- gmem scratch (static __device__), fp16 ----
__device__ __half g_qkv[(size_t)4096 * 3 * 64 * 192];  // [win][p][t][c]
__device__ __half g_o[(size_t)4096 * 64 * 192];        // [win][t][c]

__device__ __forceinline__ void mma16(float* c, const uint32_t* a, const uint32_t* b) {
    asm volatile(
        "mma.sync.aligned.m16n8k16.row.col.f32.f16.f16.f32 "
        "{%0,%1,%2,%3}, {%4,%5,%6,%7}, {%8,%9}, {%0,%1,%2,%3};"
        : "+f"(c[0]), "+f"(c[1]), "+f"(c[2]), "+f"(c[3])
        : "r"(a[0]), "r"(a[1]), "r"(a[2]), "r"(a[3]),
          "r"(b[0]), "r"(b[1]));
}

__device__ __forceinline__ uint32_t smem_u32(const void* p) {
    uint32_t a;
    asm("{ .reg .u64 t; cvta.to.shared.u64 t, %1; cvt.u32.u64 %0, t; }" : "=r"(a) : "l"(p));
    return a;
}
__device__ __forceinline__ void ldsm_x4(uint32_t* r, uint32_t addr) {
    asm volatile("ldmatrix.sync.aligned.m8n8.x4.shared.b16 {%0,%1,%2,%3}, [%4];"
        : "=r"(r[0]), "=r"(r[1]), "=r"(r[2]), "=r"(r[3]) : "r"(addr));
}
__device__ __forceinline__ void ldsm_x4t(uint32_t* r, uint32_t addr) {
    asm volatile("ldmatrix.sync.aligned.m8n8.x4.trans.shared.b16 {%0,%1,%2,%3}, [%4];"
        : "=r"(r[0]), "=r"(r[1]), "=r"(r[2]), "=r"(r[3]) : "r"(addr));
}
__device__ __forceinline__ void ldsm_x2t(uint32_t* r, uint32_t addr) {
    asm volatile("ldmatrix.sync.aligned.m8n8.x2.trans.shared.b16 {%0,%1}, [%2];"
        : "=r"(r[0]), "=r"(r[1]) : "r"(addr));
}
__device__ __forceinline__ uint32_t f22h2(float a, float b) {
    __half2 h = __floats2half2_rn(a, b);
    return *(uint32_t*)&h;
}

// =====================================================================
// Kernel A: QKV GEMM. 1 window/CTA (M=64), 256 threads, fp16 mma k16.
// warp tile m64 x n24 (mt=4, nt=3). smem: Xs half[64][200] + Wc half[32][200]
// = 38400 B -> 3 CTAs/SM.
// =====================================================================
#define LDX 200
#define LDW 200
#define Q_OFF_W (64 * 200)                 // halfs
#define Q_SMEM_BYTES ((64 * 200 + 32 * 200) * 2)   // 38400

__global__ void __launch_bounds__(256, 3)
k_qkv(const float* __restrict__ x,
      const float* __restrict__ qkv_w,
      const float* __restrict__ qkv_b)
{
    extern __shared__ __half smh[];
    __half* Xs = smh;             // [64][200]
    __half* Wc = smh + Q_OFF_W;   // [32][200]

    const int tid  = threadIdx.x;
    const int warp = tid >> 5, lane = tid & 31;
    const int grp  = lane >> 2, tig = lane & 3;
    const int rl = lane & 15, chh = (lane >> 4) * 8;
    const int win = blockIdx.x;
    const int b = win >> 10, wy = (win >> 5) & 31, wx = win & 31;
    const int baseH = wy * 8 + SHIFTc, baseW = wx * 8 + SHIFTc;

    // ---- gather window with roll -> Xs[t][c] fp16 ----
    {
        const float* xb = x + (size_t)b * Cc * 65536;
        #pragma unroll
        for (int i = 0; i < 48; ++i) {
            int idx = tid + i * 256;
            int c = idx >> 6, t = idx & 63;
            int ih = (baseH + (t >> 3)) & 255;
            int iw = (baseW + (t & 7)) & 255;
            Xs[t * LDX + c] = __float2half_rn(xb[c * 65536 + ih * 256 + iw]);
        }
    }

    const uint32_t XsU = smem_u32(Xs);
    const uint32_t WcU = smem_u32(Wc);
    const uint32_t aBase = XsU + (rl * LDX + chh) * 2;
    const uint32_t bBase = WcU + (rl * LDW + warp * 24 + chh) * 2;

    float acc[4][3][4];
    #pragma unroll
    for (int mt = 0; mt < 4; ++mt)
        #pragma unroll
        for (int nt = 0; nt < 3; ++nt)
            #pragma unroll
            for (int i = 0; i < 4; ++i) acc[mt][nt][i] = 0.0f;

    // 18 chunks: pass p = cc/6, kc = cc%6, 32 k-rows each
    #pragma unroll 1
    for (int cc = 0; cc < 18; ++cc) {
        const int kc = cc % 6;
        const int p  = cc / 6;

        __syncthreads();
        // stage W rows [kc*32,+32) cols [p*192,+192): 1536 float4, 6/thread
        #pragma unroll
        for (int j = 0; j < 6; ++j) {
            int v4 = tid + j * 256;
            int row = v4 / 48, c4 = (v4 % 48) * 4;
            float4 w = *(const float4*)(qkv_w + (size_t)(kc * 32 + row) * 576 + p * 192 + c4);
            uint2 pk;
            pk.x = f22h2(w.x, w.y);
            pk.y = f22h2(w.z, w.w);
            *(uint2*)(Wc + row * LDW + c4) = pk;
        }
        __syncthreads();

        #pragma unroll
        for (int ks = 0; ks < 2; ++ks) {
            const int kbA = kc * 32 + ks * 16;   // global k in Xs
            const int kbB = ks * 16;             // chunk-local k in Wc
            uint32_t a[4][4];
            #pragma unroll
            for (int mt = 0; mt < 4; ++mt)
                ldsm_x4(a[mt], aBase + (mt * 16 * LDX + kbA) * 2);
            uint32_t bb[3][2];
            {
                uint32_t t4[4];
                ldsm_x4t(t4, bBase + kbB * LDW * 2);
                bb[0][0] = t4[0]; bb[0][1] = t4[1];
                bb[1][0] = t4[2]; bb[1][1] = t4[3];
                ldsm_x2t(bb[2], bBase + (kbB * LDW + 16) * 2);
            }
            #pragma unroll
            for (int mt = 0; mt < 4; ++mt)
                #pragma unroll
                for (int nt = 0; nt < 3; ++nt)
                    mma16(acc[mt][nt], a[mt], bb[nt]);
        }

        // end of pass: bias + store fp16 + reset acc
        if (kc == 5) {
            #pragma unroll
            for (int nt = 0; nt < 3; ++nt) {
                int col = warp * 24 + nt * 8 + 2 * tig;
                float b0 = __ldg(qkv_b + p * 192 + col);
                float b1 = __ldg(qkv_b + p * 192 + col + 1);
                #pragma unroll
                for (int mt = 0; mt < 4; ++mt) {
                    int r = mt * 16 + grp;
                    __half* dst = g_qkv + (size_t)win * 36864 + p * 12288 + r * 192 + col;
                    *(uint32_t*)dst = f22h2(acc[mt][nt][0] + b0, acc[mt][nt][1] + b1);
                    *(uint32_t*)(dst + 8 * 192) = f22h2(acc[mt][nt][2] + b0, acc[mt][nt][3] + b1);
                    acc[mt][nt][0] = 0.0f; acc[mt][nt][1] = 0.0f;
                    acc[mt][nt][2] = 0.0f; acc[mt][nt][3] = 0.0f;
                }
            }
        }
    }
}

// =====================================================================
// Kernel B: attention per (window, head). 128 threads, fp16 mma.
// Q from gmem into fragments; S + softmax + P all in REGISTERS
// (S-fragment layout == P A-fragment layout). smem: Kh,Vh only = 10240 B.
// =====================================================================
#define LDH 40
#define LDV 40
#define B_SMEM_BYTES ((64 * 40 + 64 * 40) * 2)   // 10240

__global__ void __launch_bounds__(128, 6)
k_attn()
{
    extern __shared__ __half smh[];
    __half* Kh = smh;             // [64][40]
    __half* Vh = smh + 64 * LDH;  // [64][40]

    const int tid  = threadIdx.x;
    const int warp = tid >> 5, lane = tid & 31;
    const int grp  = lane >> 2, tig = lane & 3;
    const int rl = lane & 15, chh = (lane >> 4) * 8;
    const int win = blockIdx.x, h = blockIdx.y;

    // Q fragments direct from gmem (warp-private rows warp*16..+15)
    uint32_t qa[2][4];
    {
        const __half* qsrc = g_qkv + (size_t)win * 36864 + h * 32
                           + (warp * 16 + grp) * 192 + 2 * tig;
        #pragma unroll
        for (int kt = 0; kt < 2; ++kt) {
            qa[kt][0] = *(const uint32_t*)(qsrc + kt * 16);
            qa[kt][1] = *(const uint32_t*)(qsrc + kt * 16 + 8 * 192);
            qa[kt][2] = *(const uint32_t*)(qsrc + kt * 16 + 8);
            qa[kt][3] = *(const uint32_t*)(qsrc + kt * 16 + 8 + 8 * 192);
        }
    }

    // stage K, V head slices (16B chunks)
    {
        const __half* ksrc = g_qkv + (size_t)win * 36864 + 12288 + h * 32;
        const __half* vsrc = ksrc + 12288;
        #pragma unroll
        for (int it = 0; it < 2; ++it) {
            int idx = tid + it * 128;
            int t = idx >> 2, j = (idx & 3) * 8;
            *(uint4*)(Kh + t * LDH + j) = *(const uint4*)(ksrc + t * 192 + j);
            *(uint4*)(Vh + t * LDV + j) = *(const uint4*)(vsrc + t * 192 + j);
        }
    }
    __syncthreads();

    const uint32_t KhU = smem_u32(Kh);
    const uint32_t VhU = smem_u32(Vh);

    // S = Q @ K^T (rows warp*16..+15, all 64 cols), K=32 -> 2 k16 steps
    float sacc[8][4];
    #pragma unroll
    for (int nt = 0; nt < 8; ++nt)
        #pragma unroll
        for (int i = 0; i < 4; ++i) sacc[nt][i] = 0.0f;

    #pragma unroll
    for (int kt = 0; kt < 2; ++kt) {
        uint32_t kb4[4][4];
        #pragma unroll
        for (int ntp = 0; ntp < 4; ++ntp)
            ldsm_x4(kb4[ntp], KhU + ((ntp * 16 + rl) * LDH + kt * 16 + chh) * 2);
        #pragma unroll
        for (int nt = 0; nt < 8; ++nt) {
            uint32_t bfr[2] = { kb4[nt >> 1][nt & 1], kb4[nt >> 1][2 + (nt & 1)] };
            mma16(sacc[nt], qa[kt], bfr);
        }
    }

    // register softmax: this thread holds rows r0 = warp*16+grp ([0],[1])
    // and r1 = r0+8 ([2],[3]); row lives in the 4 lanes of the quad.
    const float scale = 0.17677669529663687f;  // 1/sqrt(32)
    float m0 = -1e30f, m1 = -1e30f;
    #pragma unroll
    for (int nt = 0; nt < 8; ++nt) {
        #pragma unroll
        for (int i = 0; i < 4; ++i) sacc[nt][i] *= scale;
        m0 = fmaxf(m0, fmaxf(sacc[nt][0], sacc[nt][1]));
        m1 = fmaxf(m1, fmaxf(sacc[nt][2], sacc[nt][3]));
    }
    m0 = fmaxf(m0, __shfl_xor_sync(0xFFFFFFFFu, m0, 1));
    m0 = fmaxf(m0, __shfl_xor_sync(0xFFFFFFFFu, m0, 2));
    m1 = fmaxf(m1, __shfl_xor_sync(0xFFFFFFFFu, m1, 1));
    m1 = fmaxf(m1, __shfl_xor_sync(0xFFFFFFFFu, m1, 2));
    float s0 = 0.0f, s1 = 0.0f;
    #pragma unroll
    for (int nt = 0; nt < 8; ++nt) {
        float e0 = __expf(sacc[nt][0] - m0); sacc[nt][0] = e0; s0 += e0;
        float e1 = __expf(sacc[nt][1] - m0); sacc[nt][1] = e1; s0 += e1;
        float e2 = __expf(sacc[nt][2] - m1); sacc[nt][2] = e2; s1 += e2;
        float e3 = __expf(sacc[nt][3] - m1); sacc[nt][3] = e3; s1 += e3;
    }
    s0 += __shfl_xor_sync(0xFFFFFFFFu, s0, 1);
    s0 += __shfl_xor_sync(0xFFFFFFFFu, s0, 2);
    s1 += __shfl_xor_sync(0xFFFFFFFFu, s1, 1);
    s1 += __shfl_xor_sync(0xFFFFFFFFu, s1, 2);
    float inv0 = __frcp_rn(s0), inv1 = __frcp_rn(s1);

    // P as fp16 A-fragments (layout identity: cols nt*8+2tig pair = k pairs)
    uint32_t pa[4][4];
    #pragma unroll
    for (int kt = 0; kt < 4; ++kt) {
        pa[kt][0] = f22h2(sacc[2 * kt][0] * inv0, sacc[2 * kt][1] * inv0);
        pa[kt][1] = f22h2(sacc[2 * kt][2] * inv1, sacc[2 * kt][3] * inv1);
        pa[kt][2] = f22h2(sacc[2 * kt + 1][0] * inv0, sacc[2 * kt + 1][1] * inv0);
        pa[kt][3] = f22h2(sacc[2 * kt + 1][2] * inv1, sacc[2 * kt + 1][3] * inv1);
    }

    // O = P @ V : m16 x n32, K=64 -> 4 k16 steps
    float oacc[4][4];
    #pragma unroll
    for (int nt = 0; nt < 4; ++nt)
        #pragma unroll
        for (int i = 0; i < 4; ++i) oacc[nt][i] = 0.0f;

    #pragma unroll
    for (int kt = 0; kt < 4; ++kt) {
        uint32_t vb[2][4];
        #pragma unroll
        for (int ntp = 0; ntp < 2; ++ntp)
            ldsm_x4t(vb[ntp], VhU + ((kt * 16 + rl) * LDV + ntp * 16 + chh) * 2);
        #pragma unroll
        for (int nt = 0; nt < 4; ++nt) {
            uint32_t bfr[2] = { vb[nt >> 1][(nt & 1) * 2], vb[nt >> 1][(nt & 1) * 2 + 1] };
            mma16(oacc[nt], pa[kt], bfr);
        }
    }

    // store O fp16
    __half* dst = g_o + (size_t)win * 12288 + (warp * 16 + grp) * 192 + h * 32;
    #pragma unroll
    for (int nt = 0; nt < 4; ++nt) {
        int col = nt * 8 + 2 * tig;
        *(uint32_t*)(dst + col) = f22h2(oacc[nt][0], oacc[nt][1]);
        *(uint32_t*)(dst + col + 8 * 192) = f22h2(oacc[nt][2], oacc[nt][3]);
    }
}

// =====================================================================
// Kernel C: proj GEMM. 1 window/CTA, 256 threads, fp16 mma, m64 x n24,
// roll-scatter fp32 epilogue. smem 38400 B -> 3 CTAs/SM.
// =====================================================================
__global__ void __launch_bounds__(256, 3)
k_proj(const float* __restrict__ proj_w,
       const float* __restrict__ proj_b,
       float* __restrict__ out)
{
    extern __shared__ __half smh[];
    __half* Os = smh;             // [64][200]
    __half* Wc = smh + Q_OFF_W;   // [32][200]

    const int tid  = threadIdx.x;
    const int warp = tid >> 5, lane = tid & 31;
    const int grp  = lane >> 2, tig = lane & 3;
    const int rl = lane & 15, chh = (lane >> 4) * 8;
    const int win = blockIdx.x;
    const int b = win >> 10, wy = (win >> 5) & 31, wx = win & 31;
    const int baseH = wy * 8 + SHIFTc, baseW = wx * 8 + SHIFTc;

    // stage O tile (fp16, 16B chunks, repack stride 192 -> 200)
    {
        const __half* src = g_o + (size_t)win * 12288;
        #pragma unroll
        for (int i = 0; i < 6; ++i) {
            int idx = tid + i * 256;            // 1536 uint4
            int t = idx / 24, j = (idx % 24) * 8;
            *(uint4*)(Os + t * LDX + j) = *(const uint4*)(src + t * 192 + j);
        }
    }

    const uint32_t OsU = smem_u32(Os);
    const uint32_t WcU = smem_u32(Wc);
    const uint32_t aBase = OsU + (rl * LDX + chh) * 2;
    const uint32_t bBase = WcU + (rl * LDW + warp * 24 + chh) * 2;

    float acc[4][3][4];
    #pragma unroll
    for (int mt = 0; mt < 4; ++mt)
        #pragma unroll
        for (int nt = 0; nt < 3; ++nt)
            #pragma unroll
            for (int i = 0; i < 4; ++i) acc[mt][nt][i] = 0.0f;

    #pragma unroll 1
    for (int kc = 0; kc < 6; ++kc) {
        __syncthreads();
        #pragma unroll
        for (int j = 0; j < 6; ++j) {
            int v4 = tid + j * 256;
            int row = v4 / 48, c4 = (v4 % 48) * 4;
            float4 w = *(const float4*)(proj_w + (size_t)(kc * 32 + row) * 192 + c4);
            uint2 pk;
            pk.x = f22h2(w.x, w.y);
            pk.y = f22h2(w.z, w.w);
            *(uint2*)(Wc + row * LDW + c4) = pk;
        }
        __syncthreads();

        #pragma unroll
        for (int ks = 0; ks < 2; ++ks) {
            const int kbA = kc * 32 + ks * 16;
            const int kbB = ks * 16;
            uint32_t a[4][4];
            #pragma unroll
            for (int mt = 0; mt < 4; ++mt)
                ldsm_x4(a[mt], aBase + (mt * 16 * LDX + kbA) * 2);
            uint32_t bb[3][2];
            {
                uint32_t t4[4];
                ldsm_x4t(t4, bBase + kbB * LDW * 2);
                bb[0][0] = t4[0]; bb[0][1] = t4[1];
                bb[1][0] = t4[2]; bb[1][1] = t4[3];
                ldsm_x2t(bb[2], bBase + (kbB * LDW + 16) * 2);
            }
            #pragma unroll
            for (int mt = 0; mt < 4; ++mt)
                #pragma unroll
                for (int nt = 0; nt < 3; ++nt)
                    mma16(acc[mt][nt], a[mt], bb[nt]);
        }
    }

    // epilogue: bias + roll-scatter straight from registers (fp32 NCHW)
    const int ow = (baseW + grp) & 255;
    #pragma unroll
    for (int nt = 0; nt < 3; ++nt) {
        int col = warp * 24 + nt * 8 + 2 * tig;
        float b0 = __ldg(proj_b + col);
        float b1 = __ldg(proj_b + col + 1);
        #pragma unroll
        for (int mt = 0; mt < 4; ++mt) {
            int t0 = mt * 16 + grp;
            int oh0 = (baseH + (t0 >> 3)) & 255;
            int oh1 = (baseH + ((t0 + 8) >> 3)) & 255;
            float* o0 = out + (size_t)b * Cc * 65536 + (size_t)col * 65536;
            float* o1 = o0 + 65536;
            o0[oh0 * 256 + ow] = acc[mt][nt][0] + b0;
            o1[oh0 * 256 + ow] = acc[mt][nt][1] + b1;
            o0[oh1 * 256 + ow] = acc[mt][nt][2] + b0;
            o1[oh1 * 256 + ow] = acc[mt][nt][3] + b1;
        }
    }
}

extern "C" void kernel_launch(void* const* d_in, const int* in_sizes, int n_in,
                              void* d_out, int out_size)
{
    const float* x      = (const float*)d_in[0];
    const float* qkv_w  = (const float*)d_in[1];
    const float* qkv_b  = (const float*)d_in[2];
    const float* proj_w = (const float*)d_in[3];
    const float* proj_b = (const float*)d_in[4];
    float* out = (float*)d_out;

    cudaFuncSetAttribute(k_qkv,  cudaFuncAttributeMaxDynamicSharedMemorySize, Q_SMEM_BYTES);
    cudaFuncSetAttribute(k_attn, cudaFuncAttributeMaxDynamicSharedMemorySize, B_SMEM_BYTES);
    cudaFuncSetAttribute(k_proj, cudaFuncAttributeMaxDynamicSharedMemorySize, Q_SMEM_BYTES);

    k_qkv<<<4096, 256, Q_SMEM_BYTES>>>(x, qkv_w, qkv_b);
    dim3 gb(4096, 6);
    k_attn<<<gb, 128, B_SMEM_BYTES>>>();
    k_proj<<<4096, 256, Q_SMEM_BYTES>>>(proj_w, proj_b, out);
}

// round 17
// speedup vs baseline: 2.0141x; 1.2468x over previous
#include <cuda_runtime.h>
#include <cuda_fp16.h>
#include <cstdint>

// Problem constants
#define Cc 192
#define SHIFTc 4

// ---- gmem scratch (static __device__), fp16 ----
__device__ __align__(16) __half g_qkv[(size_t)4096 * 3 * 64 * 192];  // [win][p][t][c]
__device__ __align__(16) __half g_o[(size_t)4096 * 64 * 192];        // [win][t][c]
__device__ __align__(16) __half g_wq[192 * 576];                     // fp16 qkv_w
__device__ __align__(16) __half g_wp[192 * 192];                     // fp16 proj_w

__device__ __forceinline__ void mma16(float* c, const uint32_t* a, const uint32_t* b) {
    asm volatile(
        "mma.sync.aligned.m16n8k16.row.col.f32.f16.f16.f32 "
        "{%0,%1,%2,%3}, {%4,%5,%6,%7}, {%8,%9}, {%0,%1,%2,%3};"
        : "+f"(c[0]), "+f"(c[1]), "+f"(c[2]), "+f"(c[3])
        : "r"(a[0]), "r"(a[1]), "r"(a[2]), "r"(a[3]),
          "r"(b[0]), "r"(b[1]));
}

__device__ __forceinline__ uint32_t smem_u32(const void* p) {
    uint32_t a;
    asm("{ .reg .u64 t; cvta.to.shared.u64 t, %1; cvt.u32.u64 %0, t; }" : "=r"(a) : "l"(p));
    return a;
}
__device__ __forceinline__ void ldsm_x4(uint32_t* r, uint32_t addr) {
    asm volatile("ldmatrix.sync.aligned.m8n8.x4.shared.b16 {%0,%1,%2,%3}, [%4];"
        : "=r"(r[0]), "=r"(r[1]), "=r"(r[2]), "=r"(r[3]) : "r"(addr));
}
__device__ __forceinline__ void ldsm_x4t(uint32_t* r, uint32_t addr) {
    asm volatile("ldmatrix.sync.aligned.m8n8.x4.trans.shared.b16 {%0,%1,%2,%3}, [%4];"
        : "=r"(r[0]), "=r"(r[1]), "=r"(r[2]), "=r"(r[3]) : "r"(addr));
}
__device__ __forceinline__ void ldsm_x2t(uint32_t* r, uint32_t addr) {
    asm volatile("ldmatrix.sync.aligned.m8n8.x2.trans.shared.b16 {%0,%1}, [%2];"
        : "=r"(r[0]), "=r"(r[1]) : "r"(addr));
}
__device__ __forceinline__ uint32_t f22h2(float a, float b) {
    __half2 h = __floats2half2_rn(a, b);
    return *(uint32_t*)&h;
}
__device__ __forceinline__ void cp16(uint32_t smem_dst, const void* gsrc) {
    asm volatile("cp.async.cg.shared.global [%0], [%1], 16;"
        :: "r"(smem_dst), "l"(gsrc) : "memory");
}
#define CP_COMMIT() asm volatile("cp.async.commit_group;" ::: "memory")
#define CP_WAIT0()  asm volatile("cp.async.wait_group 0;" ::: "memory")

// =====================================================================
// Kernel 0: one-time weight conversion fp32 -> fp16
// qkv_w: 110592 floats (27648 float4); proj_w: 36864 floats (9216 float4)
// =====================================================================
__global__ void __launch_bounds__(256)
k_cvt(const float* __restrict__ qkv_w, const float* __restrict__ proj_w)
{
    int i = blockIdx.x * 256 + threadIdx.x;    // 0..36863
    if (i < 27648) {
        float4 w = ((const float4*)qkv_w)[i];
        uint2 p;
        p.x = f22h2(w.x, w.y);
        p.y = f22h2(w.z, w.w);
        *(uint2*)(g_wq + (size_t)i * 4) = p;
    } else {
        int j = i - 27648;
        float4 w = ((const float4*)proj_w)[j];
        uint2 p;
        p.x = f22h2(w.x, w.y);
        p.y = f22h2(w.z, w.w);
        *(uint2*)(g_wp + (size_t)j * 4) = p;
    }
}

// =====================================================================
// Kernel A: QKV GEMM. 1 window/CTA (M=64), 256 threads, fp16 mma k16,
// warp tile m64 x n24. Double-buffered fp16 weight chunks via cp.async,
// ONE barrier per chunk. smem: Xs[64][200] + 2 x Wc[32][200] = 51200 B
// -> 3 CTAs/SM (regs ~80 <= 85).
// =====================================================================
#define LDX 200
#define LDW 200
#define Q_OFF_W (64 * 200)                    // halfs
#define QW_STRIDE (32 * 200)                  // halfs per W buffer
#define Q_SMEM_BYTES ((64 * 200 + 2 * 32 * 200) * 2)   // 51200

__global__ void __launch_bounds__(256, 3)
k_qkv(const float* __restrict__ x,
      const float* __restrict__ qkv_b)
{
    extern __shared__ __half smh[];
    __half* Xs = smh;             // [64][200]
    __half* Wb = smh + Q_OFF_W;   // 2 x [32][200]

    const int tid  = threadIdx.x;
    const int warp = tid >> 5, lane = tid & 31;
    const int grp  = lane >> 2, tig = lane & 3;
    const int rl = lane & 15, chh = (lane >> 4) * 8;
    const int win = blockIdx.x;
    const int b = win >> 10, wy = (win >> 5) & 31, wx = win & 31;
    const int baseH = wy * 8 + SHIFTc, baseW = wx * 8 + SHIFTc;

    // staging decomposition: chunk = 32 rows x 192 halfs = 768 uint4, 3/thread
    const int st_row = tid / 24 * 0;  // (computed per-j below)
    const uint32_t WbU[2] = { smem_u32(Wb), smem_u32(Wb + QW_STRIDE) };

    // issue cp.async for chunk cc into buffer bi
    auto issue_chunk = [&](int cc, int bi) {
        const int kc = cc % 6, p = cc / 6;
        #pragma unroll
        for (int j = 0; j < 3; ++j) {
            int v4 = tid + j * 256;
            int row = v4 / 24, c8 = (v4 % 24) * 8;
            const __half* src = g_wq + (size_t)(kc * 32 + row) * 576 + p * 192 + c8;
            cp16(WbU[bi] + (row * LDW + c8) * 2, src);
        }
        CP_COMMIT();
    };

    // prologue: start chunk 0 copy, then gather A (overlaps the copy)
    issue_chunk(0, 0);
    {
        const float* xb = x + (size_t)b * Cc * 65536;
        #pragma unroll
        for (int i = 0; i < 48; ++i) {
            int idx = tid + i * 256;
            int c = idx >> 6, t = idx & 63;
            int ih = (baseH + (t >> 3)) & 255;
            int iw = (baseW + (t & 7)) & 255;
            Xs[t * LDX + c] = __float2half_rn(xb[c * 65536 + ih * 256 + iw]);
        }
    }
    CP_WAIT0();
    __syncthreads();

    const uint32_t XsU = smem_u32(Xs);
    const uint32_t aBase = XsU + (rl * LDX + chh) * 2;
    const uint32_t bOff = (rl * LDW + warp * 24 + chh) * 2;

    float acc[4][3][4];
    #pragma unroll
    for (int mt = 0; mt < 4; ++mt)
        #pragma unroll
        for (int nt = 0; nt < 3; ++nt)
            #pragma unroll
            for (int i = 0; i < 4; ++i) acc[mt][nt][i] = 0.0f;

    #pragma unroll 1
    for (int cc = 0; cc < 18; ++cc) {
        const int kc = cc % 6;
        const int p  = cc / 6;

        // start next chunk's copy into the other buffer (safe: its previous
        // readers were fenced by the barrier at the end of last iteration)
        if (cc < 17) issue_chunk(cc + 1, (cc + 1) & 1);

        const uint32_t bBase = WbU[cc & 1] + bOff;

        #pragma unroll
        for (int ks = 0; ks < 2; ++ks) {
            const int kbA = kc * 32 + ks * 16;
            const int kbB = ks * 16;
            uint32_t a[4][4];
            #pragma unroll
            for (int mt = 0; mt < 4; ++mt)
                ldsm_x4(a[mt], aBase + (mt * 16 * LDX + kbA) * 2);
            uint32_t bb[3][2];
            {
                uint32_t t4[4];
                ldsm_x4t(t4, bBase + kbB * LDW * 2);
                bb[0][0] = t4[0]; bb[0][1] = t4[1];
                bb[1][0] = t4[2]; bb[1][1] = t4[3];
                ldsm_x2t(bb[2], bBase + (kbB * LDW + 16) * 2);
            }
            #pragma unroll
            for (int mt = 0; mt < 4; ++mt)
                #pragma unroll
                for (int nt = 0; nt < 3; ++nt)
                    mma16(acc[mt][nt], a[mt], bb[nt]);
        }

        // end of pass: bias + store fp16 + reset acc
        if (kc == 5) {
            #pragma unroll
            for (int nt = 0; nt < 3; ++nt) {
                int col = warp * 24 + nt * 8 + 2 * tig;
                float b0 = __ldg(qkv_b + p * 192 + col);
                float b1 = __ldg(qkv_b + p * 192 + col + 1);
                #pragma unroll
                for (int mt = 0; mt < 4; ++mt) {
                    int r = mt * 16 + grp;
                    __half* dst = g_qkv + (size_t)win * 36864 + p * 12288 + r * 192 + col;
                    *(uint32_t*)dst = f22h2(acc[mt][nt][0] + b0, acc[mt][nt][1] + b1);
                    *(uint32_t*)(dst + 8 * 192) = f22h2(acc[mt][nt][2] + b0, acc[mt][nt][3] + b1);
                    acc[mt][nt][0] = 0.0f; acc[mt][nt][1] = 0.0f;
                    acc[mt][nt][2] = 0.0f; acc[mt][nt][3] = 0.0f;
                }
            }
        }

        if (cc < 17) CP_WAIT0();
        __syncthreads();
    }
}

// =====================================================================
// Kernel B: attention per (window, head). 128 threads, fp16 mma,
// register softmax (S-fragment == P A-fragment). smem 10240 B.
// =====================================================================
#define LDH 40
#define LDV 40
#define B_SMEM_BYTES ((64 * 40 + 64 * 40) * 2)   // 10240

__global__ void __launch_bounds__(128, 6)
k_attn()
{
    extern __shared__ __half smh[];
    __half* Kh = smh;             // [64][40]
    __half* Vh = smh + 64 * LDH;  // [64][40]

    const int tid  = threadIdx.x;
    const int warp = tid >> 5, lane = tid & 31;
    const int grp  = lane >> 2, tig = lane & 3;
    const int rl = lane & 15, chh = (lane >> 4) * 8;
    const int win = blockIdx.x, h = blockIdx.y;

    // Q fragments direct from gmem (warp-private rows warp*16..+15)
    uint32_t qa[2][4];
    {
        const __half* qsrc = g_qkv + (size_t)win * 36864 + h * 32
                           + (warp * 16 + grp) * 192 + 2 * tig;
        #pragma unroll
        for (int kt = 0; kt < 2; ++kt) {
            qa[kt][0] = *(const uint32_t*)(qsrc + kt * 16);
            qa[kt][1] = *(const uint32_t*)(qsrc + kt * 16 + 8 * 192);
            qa[kt][2] = *(const uint32_t*)(qsrc + kt * 16 + 8);
            qa[kt][3] = *(const uint32_t*)(qsrc + kt * 16 + 8 + 8 * 192);
        }
    }

    // stage K, V head slices (16B chunks)
    {
        const __half* ksrc = g_qkv + (size_t)win * 36864 + 12288 + h * 32;
        const __half* vsrc = ksrc + 12288;
        #pragma unroll
        for (int it = 0; it < 2; ++it) {
            int idx = tid + it * 128;
            int t = idx >> 2, j = (idx & 3) * 8;
            *(uint4*)(Kh + t * LDH + j) = *(const uint4*)(ksrc + t * 192 + j);
            *(uint4*)(Vh + t * LDV + j) = *(const uint4*)(vsrc + t * 192 + j);
        }
    }
    __syncthreads();

    const uint32_t KhU = smem_u32(Kh);
    const uint32_t VhU = smem_u32(Vh);

    // S = Q @ K^T (rows warp*16..+15, all 64 cols), K=32 -> 2 k16 steps
    float sacc[8][4];
    #pragma unroll
    for (int nt = 0; nt < 8; ++nt)
        #pragma unroll
        for (int i = 0; i < 4; ++i) sacc[nt][i] = 0.0f;

    #pragma unroll
    for (int kt = 0; kt < 2; ++kt) {
        uint32_t kb4[4][4];
        #pragma unroll
        for (int ntp = 0; ntp < 4; ++ntp)
            ldsm_x4(kb4[ntp], KhU + ((ntp * 16 + rl) * LDH + kt * 16 + chh) * 2);
        #pragma unroll
        for (int nt = 0; nt < 8; ++nt) {
            uint32_t bfr[2] = { kb4[nt >> 1][nt & 1], kb4[nt >> 1][2 + (nt & 1)] };
            mma16(sacc[nt], qa[kt], bfr);
        }
    }

    // register softmax: rows r0 = warp*16+grp ([0],[1]) and r0+8 ([2],[3])
    const float scale = 0.17677669529663687f;  // 1/sqrt(32)
    float m0 = -1e30f, m1 = -1e30f;
    #pragma unroll
    for (int nt = 0; nt < 8; ++nt) {
        #pragma unroll
        for (int i = 0; i < 4; ++i) sacc[nt][i] *= scale;
        m0 = fmaxf(m0, fmaxf(sacc[nt][0], sacc[nt][1]));
        m1 = fmaxf(m1, fmaxf(sacc[nt][2], sacc[nt][3]));
    }
    m0 = fmaxf(m0, __shfl_xor_sync(0xFFFFFFFFu, m0, 1));
    m0 = fmaxf(m0, __shfl_xor_sync(0xFFFFFFFFu, m0, 2));
    m1 = fmaxf(m1, __shfl_xor_sync(0xFFFFFFFFu, m1, 1));
    m1 = fmaxf(m1, __shfl_xor_sync(0xFFFFFFFFu, m1, 2));
    float s0 = 0.0f, s1 = 0.0f;
    #pragma unroll
    for (int nt = 0; nt < 8; ++nt) {
        float e0 = __expf(sacc[nt][0] - m0); sacc[nt][0] = e0; s0 += e0;
        float e1 = __expf(sacc[nt][1] - m0); sacc[nt][1] = e1; s0 += e1;
        float e2 = __expf(sacc[nt][2] - m1); sacc[nt][2] = e2; s1 += e2;
        float e3 = __expf(sacc[nt][3] - m1); sacc[nt][3] = e3; s1 += e3;
    }
    s0 += __shfl_xor_sync(0xFFFFFFFFu, s0, 1);
    s0 += __shfl_xor_sync(0xFFFFFFFFu, s0, 2);
    s1 += __shfl_xor_sync(0xFFFFFFFFu, s1, 1);
    s1 += __shfl_xor_sync(0xFFFFFFFFu, s1, 2);
    float inv0 = __frcp_rn(s0), inv1 = __frcp_rn(s1);

    // P as fp16 A-fragments
    uint32_t pa[4][4];
    #pragma unroll
    for (int kt = 0; kt < 4; ++kt) {
        pa[kt][0] = f22h2(sacc[2 * kt][0] * inv0, sacc[2 * kt][1] * inv0);
        pa[kt][1] = f22h2(sacc[2 * kt][2] * inv1, sacc[2 * kt][3] * inv1);
        pa[kt][2] = f22h2(sacc[2 * kt + 1][0] * inv0, sacc[2 * kt + 1][1] * inv0);
        pa[kt][3] = f22h2(sacc[2 * kt + 1][2] * inv1, sacc[2 * kt + 1][3] * inv1);
    }

    // O = P @ V : m16 x n32, K=64 -> 4 k16 steps
    float oacc[4][4];
    #pragma unroll
    for (int nt = 0; nt < 4; ++nt)
        #pragma unroll
        for (int i = 0; i < 4; ++i) oacc[nt][i] = 0.0f;

    #pragma unroll
    for (int kt = 0; kt < 4; ++kt) {
        uint32_t vb[2][4];
        #pragma unroll
        for (int ntp = 0; ntp < 2; ++ntp)
            ldsm_x4t(vb[ntp], VhU + ((kt * 16 + rl) * LDV + ntp * 16 + chh) * 2);
        #pragma unroll
        for (int nt = 0; nt < 4; ++nt) {
            uint32_t bfr[2] = { vb[nt >> 1][(nt & 1) * 2], vb[nt >> 1][(nt & 1) * 2 + 1] };
            mma16(oacc[nt], pa[kt], bfr);
        }
    }

    // store O fp16
    __half* dst = g_o + (size_t)win * 12288 + (warp * 16 + grp) * 192 + h * 32;
    #pragma unroll
    for (int nt = 0; nt < 4; ++nt) {
        int col = nt * 8 + 2 * tig;
        *(uint32_t*)(dst + col) = f22h2(oacc[nt][0], oacc[nt][1]);
        *(uint32_t*)(dst + col + 8 * 192) = f22h2(oacc[nt][2], oacc[nt][3]);
    }
}

// =====================================================================
// Kernel C: proj GEMM. 1 window/CTA, 256 threads, fp16 mma, m64 x n24,
// cp.async double-buffered fp16 W, roll-scatter fp32 epilogue.
// smem 51200 B -> 3 CTAs/SM.
// =====================================================================
__global__ void __launch_bounds__(256, 3)
k_proj(const float* __restrict__ proj_b,
       float* __restrict__ out)
{
    extern __shared__ __half smh[];
    __half* Os = smh;             // [64][200]
    __half* Wb = smh + Q_OFF_W;   // 2 x [32][200]

    const int tid  = threadIdx.x;
    const int warp = tid >> 5, lane = tid & 31;
    const int grp  = lane >> 2, tig = lane & 3;
    const int rl = lane & 15, chh = (lane >> 4) * 8;
    const int win = blockIdx.x;
    const int b = win >> 10, wy = (win >> 5) & 31, wx = win & 31;
    const int baseH = wy * 8 + SHIFTc, baseW = wx * 8 + SHIFTc;

    const uint32_t WbU[2] = { smem_u32(Wb), smem_u32(Wb + QW_STRIDE) };

    auto issue_chunk = [&](int kc, int bi) {
        #pragma unroll
        for (int j = 0; j < 3; ++j) {
            int v4 = tid + j * 256;
            int row = v4 / 24, c8 = (v4 % 24) * 8;
            const __half* src = g_wp + (size_t)(kc * 32 + row) * 192 + c8;
            cp16(WbU[bi] + (row * LDW + c8) * 2, src);
        }
        CP_COMMIT();
    };

    // prologue: start chunk 0, stage O tile (overlaps)
    issue_chunk(0, 0);
    {
        const __half* src = g_o + (size_t)win * 12288;
        #pragma unroll
        for (int i = 0; i < 6; ++i) {
            int idx = tid + i * 256;            // 1536 uint4
            int t = idx / 24, j = (idx % 24) * 8;
            *(uint4*)(Os + t * LDX + j) = *(const uint4*)(src + t * 192 + j);
        }
    }
    CP_WAIT0();
    __syncthreads();

    const uint32_t OsU = smem_u32(Os);
    const uint32_t aBase = OsU + (rl * LDX + chh) * 2;
    const uint32_t bOff = (rl * LDW + warp * 24 + chh) * 2;

    float acc[4][3][4];
    #pragma unroll
    for (int mt = 0; mt < 4; ++mt)
        #pragma unroll
        for (int nt = 0; nt < 3; ++nt)
            #pragma unroll
            for (int i = 0; i < 4; ++i) acc[mt][nt][i] = 0.0f;

    #pragma unroll 1
    for (int kc = 0; kc < 6; ++kc) {
        if (kc < 5) issue_chunk(kc + 1, (kc + 1) & 1);
        const uint32_t bBase = WbU[kc & 1] + bOff;

        #pragma unroll
        for (int ks = 0; ks < 2; ++ks) {
            const int kbA = kc * 32 + ks * 16;
            const int kbB = ks * 16;
            uint32_t a[4][4];
            #pragma unroll
            for (int mt = 0; mt < 4; ++mt)
                ldsm_x4(a[mt], aBase + (mt * 16 * LDX + kbA) * 2);
            uint32_t bb[3][2];
            {
                uint32_t t4[4];
                ldsm_x4t(t4, bBase + kbB * LDW * 2);
                bb[0][0] = t4[0]; bb[0][1] = t4[1];
                bb[1][0] = t4[2]; bb[1][1] = t4[3];
                ldsm_x2t(bb[2], bBase + (kbB * LDW + 16) * 2);
            }
            #pragma unroll
            for (int mt = 0; mt < 4; ++mt)
                #pragma unroll
                for (int nt = 0; nt < 3; ++nt)
                    mma16(acc[mt][nt], a[mt], bb[nt]);
        }

        if (kc < 5) {
            CP_WAIT0();
            __syncthreads();
        }
    }

    // epilogue: bias + roll-scatter straight from registers (fp32 NCHW)
    const int ow = (baseW + grp) & 255;
    #pragma unroll
    for (int nt = 0; nt < 3; ++nt) {
        int col = warp * 24 + nt * 8 + 2 * tig;
        float b0 = __ldg(proj_b + col);
        float b1 = __ldg(proj_b + col + 1);
        #pragma unroll
        for (int mt = 0; mt < 4; ++mt) {
            int t0 = mt * 16 + grp;
            int oh0 = (baseH + (t0 >> 3)) & 255;
            int oh1 = (baseH + ((t0 + 8) >> 3)) & 255;
            float* o0 = out + (size_t)b * Cc * 65536 + (size_t)col * 65536;
            float* o1 = o0 + 65536;
            o0[oh0 * 256 + ow] = acc[mt][nt][0] + b0;
            o1[oh0 * 256 + ow] = acc[mt][nt][1] + b1;
            o0[oh1 * 256 + ow] = acc[mt][nt][2] + b0;
            o1[oh1 * 256 + ow] = acc[mt][nt][3] + b1;
        }
    }
}

extern "C" void kernel_launch(void* const* d_in, const int* in_sizes, int n_in,
                              void* d_out, int out_size)
{
    const float* x      = (const float*)d_in[0];
    const float* qkv_w  = (const float*)d_in[1];
    const float* qkv_b  = (const float*)d_in[2];
    const float* proj_w = (const float*)d_in[3];
    const float* proj_b = (const float*)d_in[4];
    float* out = (float*)d_out;

    cudaFuncSetAttribute(k_qkv,  cudaFuncAttributeMaxDynamicSharedMemorySize, Q_SMEM_BYTES);
    cudaFuncSetAttribute(k_attn, cudaFuncAttributeMaxDynamicSharedMemorySize, B_SMEM_BYTES);
    cudaFuncSetAttribute(k_proj, cudaFuncAttributeMaxDynamicSharedMemorySize, Q_SMEM_BYTES);

    k_cvt<<<144, 256>>>(qkv_w, proj_w);
    k_qkv<<<4096, 256, Q_SMEM_BYTES>>>(x, qkv_b);
    dim3 gb(4096, 6);
    k_attn<<<gb, 128, B_SMEM_BYTES>>>();
    k_proj<<<4096, 256, Q_SMEM_BYTES>>>(proj_b, out);
}